// round 13
// baseline (speedup 1.0000x reference)
#include <cuda_runtime.h>
#include <cuda_bf16.h>
#include <cstdint>

// Problem constants (fixed by the reference setup)
#define MTOK 8192      // B*T
#define TLEN 2048
#define HDIM 4096
#define DBOT 1024
#define PP   8
#define DD   64
#define COMBDIM 128

// Does this compilation pass support tcgen05 (sm_103a arch-specific)?
#if defined(__CUDA_ARCH__) && (defined(__CUDA_ARCH_FEAT_SM103_ALL) || defined(__CUDA_ARCH_SPECIFIC__))
#define HAS_TCGEN05 1
#else
#define HAS_TCGEN05 0
#endif

// ---------------- scratch (device globals) ---------------------------------
__device__ float          g_hbot   [(size_t)MTOK * DBOT];      // fp32 h_bot
__device__ float          g_bf     [(size_t)MTOK * DBOT];      // base|fiber [8192,1024]
__device__ float          g_wlog   [(size_t)MTOK * PP];
__device__ __nv_bfloat16  g_comb_bf[(size_t)MTOK * COMBDIM];
__device__ __nv_bfloat16  g_wiT    [(size_t)DBOT * HDIM];      // Wi^T  [1024,4096]
__device__ __nv_bfloat16  g_w23T   [(size_t)DBOT * DBOT];      // [Wb|Wf]^T [1024,1024]
__device__ __nv_bfloat16  g_woT    [(size_t)HDIM * COMBDIM];   // Wo^T  [4096,128]
__device__ float          g_bias23 [DBOT];

// ---------------- common PTX helpers (sm_80+) ------------------------------
__device__ __forceinline__ uint32_t smem_u32(const void* p) {
    uint32_t a;
    asm("{ .reg .u64 t; cvta.to.shared.u64 t, %1; cvt.u32.u64 %0, t; }" : "=r"(a) : "l"(p));
    return a;
}
__device__ __forceinline__ void cp16(uint32_t s, const void* g) {
    asm volatile("cp.async.cg.shared.global [%0], [%1], 16;" :: "r"(s), "l"(g));
}
__device__ __forceinline__ void cp_commit() { asm volatile("cp.async.commit_group;"); }
__device__ __forceinline__ void cp_wait0()  { asm volatile("cp.async.wait_group 0;"); }
__device__ __forceinline__ void cp_wait1()  { asm volatile("cp.async.wait_group 1;"); }

__device__ __forceinline__ void sts128(uint32_t addr, uint32_t a, uint32_t b,
                                       uint32_t c, uint32_t d) {
    asm volatile("st.shared.v4.b32 [%0], {%1,%2,%3,%4};"
                 :: "r"(addr), "r"(a), "r"(b), "r"(c), "r"(d) : "memory");
}
__device__ __forceinline__ uint32_t pack_bf16(float lo, float hi) {
    __nv_bfloat162 h = __floats2bfloat162_rn(lo, hi);
    return *reinterpret_cast<uint32_t*>(&h);
}
__device__ __forceinline__ void ldm_x4(uint32_t& r0, uint32_t& r1, uint32_t& r2, uint32_t& r3,
                                       uint32_t addr) {
    asm volatile("ldmatrix.sync.aligned.m8n8.x4.shared.b16 {%0,%1,%2,%3}, [%4];"
                 : "=r"(r0), "=r"(r1), "=r"(r2), "=r"(r3) : "r"(addr));
}
__device__ __forceinline__ void mma_bf16(float* d, const uint32_t* a, const uint32_t* b) {
    asm volatile("mma.sync.aligned.m16n8k16.row.col.f32.bf16.bf16.f32 "
                 "{%0,%1,%2,%3}, {%4,%5,%6,%7}, {%8,%9}, {%0,%1,%2,%3};"
                 : "+f"(d[0]), "+f"(d[1]), "+f"(d[2]), "+f"(d[3])
                 : "r"(a[0]), "r"(a[1]), "r"(a[2]), "r"(a[3]), "r"(b[0]), "r"(b[1]));
}
__device__ __forceinline__ uint32_t swz(uint32_t o) { return o ^ ((o >> 3) & 0x70u); }

// ---------------- tcgen05 helpers (sm_103a pass only) ----------------------
#if HAS_TCGEN05
__device__ __forceinline__ uint32_t elect_one() {
    uint32_t pred;
    asm volatile("{\n\t.reg .pred p;\n\telect.sync _|p, 0xFFFFFFFF;\n\t"
                 "selp.b32 %0, 1, 0, p;\n\t}" : "=r"(pred));
    return pred;
}
__device__ __forceinline__ void mbar_init(uint32_t a, uint32_t cnt) {
    asm volatile("mbarrier.init.shared.b64 [%0], %1;" :: "r"(a), "r"(cnt) : "memory");
}
__device__ __forceinline__ void mbar_wait(uint32_t a, uint32_t parity) {
    uint32_t done;
    do {
        asm volatile("{\n\t.reg .pred p;\n\t"
            "mbarrier.try_wait.parity.acquire.cta.shared::cta.b64 p, [%1], %2, 0x989680;\n\t"
            "selp.b32 %0, 1, 0, p;\n\t}"
            : "=r"(done) : "r"(a), "r"(parity) : "memory");
    } while (!done);
}
// .noinc is load-bearing (R10 deadlock post-mortem): it consumes a preset
// expected arrival; the default form is net-zero against the init count.
__device__ __forceinline__ void cp_mbar_arrive_noinc(uint32_t a) {
    asm volatile("cp.async.mbarrier.arrive.noinc.shared::cta.b64 [%0];" :: "r"(a) : "memory");
}
__device__ __forceinline__ void mbar_arrive(uint32_t a) {
    asm volatile("mbarrier.arrive.shared.b64 _, [%0];" :: "r"(a) : "memory");
}
__device__ __forceinline__ void tmem_alloc(uint32_t smem_dst, uint32_t ncols) {
    asm volatile("tcgen05.alloc.cta_group::1.sync.aligned.shared::cta.b32 [%0], %1;"
                 :: "r"(smem_dst), "r"(ncols) : "memory");
}
__device__ __forceinline__ void tmem_dealloc(uint32_t tmem, uint32_t ncols) {
    asm volatile("tcgen05.relinquish_alloc_permit.cta_group::1.sync.aligned;");
    asm volatile("tcgen05.dealloc.cta_group::1.sync.aligned.b32 %0, %1;" :: "r"(tmem), "r"(ncols));
}
__device__ __forceinline__ void mma_f16_ss(uint32_t d, uint64_t adesc, uint64_t bdesc,
                                           uint32_t idesc, uint32_t enable) {
    asm volatile("{\n\t.reg .pred p;\n\tsetp.ne.u32 p, %4, 0;\n\t"
        "tcgen05.mma.cta_group::1.kind::f16 [%0], %1, %2, %3, {%5, %5, %5, %5}, p;\n\t}"
        :: "r"(d), "l"(adesc), "l"(bdesc), "r"(idesc), "r"(enable), "r"(0u) : "memory");
}
__device__ __forceinline__ void mma_commit(uint32_t mbar) {
    asm volatile("tcgen05.commit.cta_group::1.mbarrier::arrive::one.shared::cluster.b64 [%0];"
                 :: "r"(mbar) : "memory");
}
__device__ __forceinline__ void ldtm_x32(uint32_t* r, uint32_t tmem) {
    asm volatile("tcgen05.ld.sync.aligned.32x32b.x32.b32 "
        "{%0,%1,%2,%3,%4,%5,%6,%7,%8,%9,%10,%11,%12,%13,%14,%15,"
        "%16,%17,%18,%19,%20,%21,%22,%23,%24,%25,%26,%27,%28,%29,%30,%31}, [%32];"
        : "=r"(r[0]),"=r"(r[1]),"=r"(r[2]),"=r"(r[3]),"=r"(r[4]),"=r"(r[5]),"=r"(r[6]),"=r"(r[7]),
          "=r"(r[8]),"=r"(r[9]),"=r"(r[10]),"=r"(r[11]),"=r"(r[12]),"=r"(r[13]),"=r"(r[14]),"=r"(r[15]),
          "=r"(r[16]),"=r"(r[17]),"=r"(r[18]),"=r"(r[19]),"=r"(r[20]),"=r"(r[21]),"=r"(r[22]),"=r"(r[23]),
          "=r"(r[24]),"=r"(r[25]),"=r"(r[26]),"=r"(r[27]),"=r"(r[28]),"=r"(r[29]),"=r"(r[30]),"=r"(r[31])
        : "r"(tmem));
}
__device__ __forceinline__ void tmem_wait_ld()  { asm volatile("tcgen05.wait::ld.sync.aligned;" ::: "memory"); }
__device__ __forceinline__ void tc_fence_after(){ asm volatile("tcgen05.fence::after_thread_sync;" ::: "memory"); }
__device__ __forceinline__ void fence_async()   { asm volatile("fence.proxy.async.shared::cta;" ::: "memory"); }

static constexpr uint64_t DESC_BASE_SW128 =
    (uint64_t(2) << 61) | (uint64_t(1) << 46) | (uint64_t(64) << 32) | (uint64_t(1) << 16);
__device__ __forceinline__ uint64_t mk_desc(uint32_t addr) {
    return DESC_BASE_SW128 | ((uint64_t)(addr >> 4) & 0x3FFFull);
}
// idesc: kind::f16, dtype=F32, atype=btype=BF16, M=128, N=128
static constexpr uint32_t IDESC =
    (1u << 4) | (1u << 7) | (1u << 10) | ((128u / 8) << 17) | ((128u / 16) << 24);
#endif  // HAS_TCGEN05

// ---------------------------------------------------------------------------
// bf16 tensor-core GEMM: C[M,N] = A[M,K] @ Bw[N,K](bf16 K-major)^T
// A is bf16 K-major (AFP32=0) or fp32 K-major converted in-producer (AFP32=1).
// CTA tile 256x256, BK=64, 256 threads. Warp-specialized tcgen05 pipeline:
//   warps 0-3 producers, warp 4 elect issues 16 MMA atoms/stage, 3-stage ring.
// MODE 1: C -> Cf(+bias).  MODE 2: C -> Cf(+bias+res).
// ---------------------------------------------------------------------------
#define STAGE_BYTES 65536u     // A0(16K) A1(16K) B0(16K) B1(16K)

template<int MODE, int AFP32>
__global__ __launch_bounds__(256)
void mma_gemm(const void* __restrict__ A,
              const __nv_bfloat16* __restrict__ Bw,
              const float* __restrict__ bias,
              const float* __restrict__ res,
              float* __restrict__ Cf,
              int N, int K)
{
#if HAS_TCGEN05
    // ============ tcgen05 warp-specialized pipeline =========================
    extern __shared__ char dsm[];
    __shared__ uint32_t s_tmem;
    __shared__ __align__(8) uint64_t s_full[3], s_empty[3], s_fin;

    const int tid = threadIdx.x;
    const int wid = tid >> 5;
    const int lid = tid & 31;
    const int n0 = blockIdx.x * 256;
    const int m0 = blockIdx.y * 256;

    const uint32_t tile0 = (smem_u32(dsm) + 1023u) & ~1023u;
    uint32_t fullb[3], emptyb[3];
#pragma unroll
    for (int b = 0; b < 3; b++) {
        fullb[b]  = smem_u32(&s_full[b]);
        emptyb[b] = smem_u32(&s_empty[b]);
    }
    const uint32_t finb = smem_u32(&s_fin);

    if (wid == 0) tmem_alloc(smem_u32(&s_tmem), 512);
    if (tid == 0) {
#pragma unroll
        for (int b = 0; b < 3; b++) {
            mbar_init(fullb[b], AFP32 ? 256 : 128);   // 128 noinc (+128 STS arrives if AFP32)
            mbar_init(emptyb[b], 1);
        }
        mbar_init(finb, 1);
    }
    __syncthreads();
    uint32_t tmem;
    asm volatile("ld.shared.b32 %0, [%1];" : "=r"(tmem) : "r"(smem_u32(&s_tmem)));

    const int steps = K >> 6;

    if (tid < 128) {
        // ---------------- producers (warps 0-3) ----------------------------
        // Stage = 512 rows x 128B (A rows 0-255, B rows 256-511).
        // thread t: rt = t>>3 (0..15), off = (t&7)*16 bytes in bf16 row.
        const int rt  = tid >> 3;
        const int off = (tid & 7) * 16;
        const uint32_t soff = (uint32_t)(off ^ ((rt & 7) << 4));
        const int aelem = (tid & 7) * 8;     // bf16 element index = fp32 element index
        const __nv_bfloat16* Bbase = Bw + (size_t)(n0 + rt) * K + (off >> 1);
        const float*         Af    = (const float*)A;
        const __nv_bfloat16* Ab    = (const __nv_bfloat16*)A;

        int php[3] = {0, 0, 0};
        for (int c = 0; c < steps; c++) {
            const int b = c % 3;
            if (c >= 3) { mbar_wait(emptyb[b], php[b]); php[b] ^= 1; }
            const uint32_t sbase = tile0 + (uint32_t)b * STAGE_BYTES;

            if (AFP32) {
                // B via cp.async, then noinc arrive covering the B cps
                const __nv_bfloat16* bg = Bbase + c * 64;
#pragma unroll
                for (int j = 0; j < 16; j++)
                    cp16(sbase + (uint32_t)(256 + j * 16 + rt) * 128u + soff,
                         bg + (size_t)j * 16 * K);
                cp_mbar_arrive_noinc(fullb[b]);
                // A: fp32 LDG -> bf16 cvt -> STS
#pragma unroll
                for (int j = 0; j < 16; j++) {
                    const float* s = Af + (size_t)(m0 + j * 16 + rt) * K + c * 64 + aelem;
                    float4 u0 = *reinterpret_cast<const float4*>(s);
                    float4 u1 = *reinterpret_cast<const float4*>(s + 4);
                    sts128(sbase + (uint32_t)(j * 16 + rt) * 128u + soff,
                           pack_bf16(u0.x, u0.y), pack_bf16(u0.z, u0.w),
                           pack_bf16(u1.x, u1.y), pack_bf16(u1.z, u1.w));
                }
                fence_async();               // make STS visible to async proxy
                mbar_arrive(fullb[b]);       // regular arrive (counts 1 of 256)
            } else {
                const __nv_bfloat16* ag = Ab + (size_t)(m0 + rt) * K + (off >> 1) + c * 64;
                const __nv_bfloat16* bg = Bbase + c * 64;
#pragma unroll
                for (int j = 0; j < 16; j++)
                    cp16(sbase + (uint32_t)(j * 16 + rt) * 128u + soff,
                         ag + (size_t)j * 16 * K);
#pragma unroll
                for (int j = 0; j < 16; j++)
                    cp16(sbase + (uint32_t)(256 + j * 16 + rt) * 128u + soff,
                         bg + (size_t)j * 16 * K);
                cp_mbar_arrive_noinc(fullb[b]);   // after ALL cps of this stage
            }
        }
    } else if (wid == 4) {
        // ---------------- MMA issuer (warp 4, one thread) -------------------
        if (elect_one()) {
            int phm[3] = {0, 0, 0};
            for (int c = 0; c < steps; c++) {
                const int b = c % 3;
                mbar_wait(fullb[b], phm[b]); phm[b] ^= 1;
                const uint32_t sbase = tile0 + (uint32_t)b * STAGE_BYTES;
                const uint64_t ad0 = mk_desc(sbase);
                const uint64_t ad1 = mk_desc(sbase + 16384u);
                const uint64_t bd0 = mk_desc(sbase + 32768u);
                const uint64_t bd1 = mk_desc(sbase + 49152u);
#pragma unroll
                for (int ss = 0; ss < 4; ss++) {
                    const uint32_t en = (c > 0 || ss > 0) ? 1u : 0u;
                    mma_f16_ss(tmem,       ad0 + ss * 2, bd0 + ss * 2, IDESC, en);
                    mma_f16_ss(tmem + 128, ad1 + ss * 2, bd0 + ss * 2, IDESC, en);
                    mma_f16_ss(tmem + 256, ad0 + ss * 2, bd1 + ss * 2, IDESC, en);
                    mma_f16_ss(tmem + 384, ad1 + ss * 2, bd1 + ss * 2, IDESC, en);
                }
                mma_commit(emptyb[b]);
            }
            mma_commit(finb);
        }
    }
    // warps 5-7 fall through to the epilogue barrier

    __syncthreads();
    mbar_wait(finb, 0);
    tc_fence_after();

    // epilogue: warps 0-3 -> m-half 0, warps 4-7 -> m-half 1.
    const int row = m0 + wid * 32 + lid;
    const uint32_t dm = tmem + (uint32_t)((wid >> 2) * 128);
#pragma unroll
    for (int nb = 0; nb < 8; nb++) {
        uint32_t r[32];
        ldtm_x32(r, dm + (uint32_t)((nb >> 2) * 256 + (nb & 3) * 32));
        tmem_wait_ld();
#pragma unroll
        for (int j = 0; j < 32; j += 4) {
            const int n = n0 + nb * 32 + j;
            float4 bv = *reinterpret_cast<const float4*>(bias + n);
            float4 v;
            v.x = __uint_as_float(r[j + 0]) + bv.x;
            v.y = __uint_as_float(r[j + 1]) + bv.y;
            v.z = __uint_as_float(r[j + 2]) + bv.z;
            v.w = __uint_as_float(r[j + 3]) + bv.w;
            if (MODE == 2) {
                float4 rv = *reinterpret_cast<const float4*>(res + (size_t)row * N + n);
                v.x += rv.x; v.y += rv.y; v.z += rv.z; v.w += rv.w;
            }
            *reinterpret_cast<float4*>(Cf + (size_t)row * N + n) = v;
        }
    }

    __syncthreads();
    if (wid == 0) tmem_dealloc(tmem, 512);

#else
    // ============ mma.sync fallback: four 128x128 quadrants (never runs) ====
    extern __shared__ char dsm[];
    const uint32_t tile0 = (smem_u32(dsm) + 1023u) & ~1023u;

    const int tid  = threadIdx.x;
    const int lane = tid & 31;
    const int wid  = tid >> 5;
    const int wm   = wid & 3;
    const int wn   = wid >> 2;

    const int ldr = tid >> 1;
    const int ldc = (tid & 1) * 4;

    const int grp = lane >> 3;
    const int l7  = lane & 7;
    const uint32_t a_row = (uint32_t)((grp & 1) * 8 + l7);
    const uint32_t a_kb  = (uint32_t)((grp >> 1) * 16);
    const uint32_t b_row = (uint32_t)((grp >> 1) * 8 + l7);
    const uint32_t b_kb  = (uint32_t)((grp & 1) * 16);

    const int steps = K >> 6;
    const float*         Af = (const float*)A;
    const __nv_bfloat16* Ab = (const __nv_bfloat16*)A;

    for (int hm = 0; hm < 2; hm++)
    for (int hn = 0; hn < 2; hn++) {
        const int m0 = blockIdx.y * 256 + hm * 128;
        const int n0 = blockIdx.x * 256 + hn * 128;

        float acc[2][8][4];
#pragma unroll
        for (int i = 0; i < 2; i++)
#pragma unroll
            for (int j = 0; j < 8; j++)
#pragma unroll
                for (int v = 0; v < 4; v++) acc[i][j][v] = 0.0f;

        auto load_stage = [&](int c) {
            const uint32_t sb = tile0 + (uint32_t)(c & 1) * 32768u;
            if (AFP32) {
#pragma unroll
                for (int g = 0; g < 4; g++) {
                    const float* s = Af + (size_t)(m0 + ldr) * K + c * 64 + (ldc + g) * 8;
                    float4 u0 = *reinterpret_cast<const float4*>(s);
                    float4 u1 = *reinterpret_cast<const float4*>(s + 4);
                    sts128(sb + swz((uint32_t)ldr * 128u + (uint32_t)(ldc + g) * 16u),
                           pack_bf16(u0.x, u0.y), pack_bf16(u0.z, u0.w),
                           pack_bf16(u1.x, u1.y), pack_bf16(u1.z, u1.w));
                }
            } else {
                const __nv_bfloat16* ag = Ab + (size_t)(m0 + ldr) * K + c * 64;
#pragma unroll
                for (int g = 0; g < 4; g++) {
                    const uint32_t co = (uint32_t)(ldc + g) * 16u;
                    cp16(sb + swz((uint32_t)ldr * 128u + co), ag + (ldc + g) * 8);
                }
            }
            const __nv_bfloat16* bg = Bw + (size_t)(n0 + ldr) * K + c * 64;
#pragma unroll
            for (int g = 0; g < 4; g++) {
                const uint32_t co = (uint32_t)(ldc + g) * 16u;
                cp16(sb + 16384u + swz((uint32_t)ldr * 128u + co), bg + (ldc + g) * 8);
            }
            cp_commit();
        };

        load_stage(0);
        if (steps > 1) load_stage(1);

        for (int s = 0; s < steps; s++) {
            if (s + 2 <= steps) cp_wait1(); else cp_wait0();
            __syncthreads();

            const uint32_t sA = tile0 + (uint32_t)(s & 1) * 32768u;
            const uint32_t sB = sA + 16384u;

#pragma unroll
            for (int ks = 0; ks < 4; ks++) {
                const uint32_t kbase = (uint32_t)ks * 32u;
                uint32_t af[2][4];
#pragma unroll
                for (int mt = 0; mt < 2; mt++) {
                    const uint32_t r = (uint32_t)(wm * 32 + mt * 16) + a_row;
                    ldm_x4(af[mt][0], af[mt][1], af[mt][2], af[mt][3],
                           sA + swz(r * 128u + kbase + a_kb));
                }
                uint32_t bf_[8][2];
#pragma unroll
                for (int nt2 = 0; nt2 < 4; nt2++) {
                    const uint32_t r = (uint32_t)(wn * 64 + nt2 * 16) + b_row;
                    uint32_t r0, r1, r2, r3;
                    ldm_x4(r0, r1, r2, r3, sB + swz(r * 128u + kbase + b_kb));
                    bf_[nt2 * 2 + 0][0] = r0; bf_[nt2 * 2 + 0][1] = r1;
                    bf_[nt2 * 2 + 1][0] = r2; bf_[nt2 * 2 + 1][1] = r3;
                }
#pragma unroll
                for (int mt = 0; mt < 2; mt++)
#pragma unroll
                    for (int nt = 0; nt < 8; nt++)
                        mma_bf16(acc[mt][nt], af[mt], bf_[nt]);
            }

            __syncthreads();
            if (s + 2 < steps) load_stage(s + 2);
        }

#pragma unroll
        for (int mt = 0; mt < 2; mt++) {
            const int rbase = m0 + wm * 32 + mt * 16 + (lane >> 2);
#pragma unroll
            for (int nt = 0; nt < 8; nt++) {
                const int col = n0 + wn * 64 + nt * 8 + 2 * (lane & 3);
                const float2 bv = *reinterpret_cast<const float2*>(bias + col);
#pragma unroll
                for (int h = 0; h < 2; h++) {
                    const int row = rbase + h * 8;
                    float2 v;
                    v.x = acc[mt][nt][h * 2 + 0] + bv.x;
                    v.y = acc[mt][nt][h * 2 + 1] + bv.y;
                    if (MODE == 2) {
                        float2 rv = *reinterpret_cast<const float2*>(res + (size_t)row * N + col);
                        v.x += rv.x; v.y += rv.y;
                    }
                    *reinterpret_cast<float2*>(Cf + (size_t)row * N + col) = v;
                }
            }
        }
        __syncthreads();
    }
#endif
}

// ---------------------------------------------------------------------------
// weightprep: all weight transposes/casts + bias concat in ONE kernel.
//  blocks [0,4096):    Wi [4096,1024] -> wiT [1024,4096]
//  blocks [4096,4608): Wb [1024,512]  -> w23T rows [0,512)
//  blocks [4608,5120): Wf [1024,512]  -> w23T rows [512,1024)
//  blocks [5120,5632): Wo [128,4096]  -> woT [4096,128]
//  block  5632:        bias23 = [bb|bf]
// ---------------------------------------------------------------------------
__global__ __launch_bounds__(256)
void weightprep_kernel(const float* __restrict__ Wi, const float* __restrict__ Wb,
                       const float* __restrict__ Wf, const float* __restrict__ Wo,
                       const float* __restrict__ bb, const float* __restrict__ bf)
{
    __shared__ float t[32][33];
    const int id = blockIdx.x;

    const float* in; __nv_bfloat16* out; int K, N, n0, k0;
    if (id < 4096)      { in = Wi; out = g_wiT;  K = HDIM;    N = DBOT; n0 = (id & 31) * 32;  k0 = (id >> 5) * 32; }
    else if (id < 4608) { int l = id - 4096; in = Wb; out = g_w23T; K = DBOT; N = 512; n0 = (l & 15) * 32; k0 = (l >> 4) * 32; }
    else if (id < 5120) { int l = id - 4608; in = Wf; out = g_w23T + (size_t)512 * DBOT; K = DBOT; N = 512; n0 = (l & 15) * 32; k0 = (l >> 4) * 32; }
    else if (id < 5632) { int l = id - 5120; in = Wo; out = g_woT;  K = COMBDIM; N = HDIM; n0 = (l & 127) * 32; k0 = (l >> 7) * 32; }
    else {
        for (int i = threadIdx.x; i < 512; i += 256) {
            g_bias23[i]       = bb[i];
            g_bias23[i + 512] = bf[i];
        }
        return;
    }

    const int tx = threadIdx.x & 31, ty = threadIdx.x >> 5;   // 32 x 8
#pragma unroll
    for (int i = 0; i < 32; i += 8)
        t[ty + i][tx] = in[(size_t)(k0 + ty + i) * N + n0 + tx];
    __syncthreads();
#pragma unroll
    for (int i = 0; i < 32; i += 8)
        out[(size_t)(n0 + ty + i) * K + k0 + tx] = __float2bfloat16(t[tx][ty + i]);
}

// ---------------------------------------------------------------------------
// w_logits (fp32, reads fp32 h_bot): warp per token, coalesced Ww rows
// ---------------------------------------------------------------------------
__global__ __launch_bounds__(256)
void wlog_kernel(const float* __restrict__ Ww, const float* __restrict__ bw)
{
    const int warp = threadIdx.x >> 5;
    const int lane = threadIdx.x & 31;
    const int t = blockIdx.x * 8 + warp;
    const float* h = g_hbot + (size_t)t * DBOT;

    float acc[PP];
#pragma unroll
    for (int p = 0; p < PP; p++) acc[p] = 0.0f;
#pragma unroll 4
    for (int k = lane; k < DBOT; k += 32) {
        const float hv = h[k];
        float4 w0 = *reinterpret_cast<const float4*>(Ww + (size_t)k * PP);
        float4 w1 = *reinterpret_cast<const float4*>(Ww + (size_t)k * PP + 4);
        acc[0] = fmaf(hv, w0.x, acc[0]); acc[1] = fmaf(hv, w0.y, acc[1]);
        acc[2] = fmaf(hv, w0.z, acc[2]); acc[3] = fmaf(hv, w0.w, acc[3]);
        acc[4] = fmaf(hv, w1.x, acc[4]); acc[5] = fmaf(hv, w1.y, acc[5]);
        acc[6] = fmaf(hv, w1.z, acc[6]); acc[7] = fmaf(hv, w1.w, acc[7]);
    }
#pragma unroll
    for (int p = 0; p < PP; p++)
#pragma unroll
        for (int o = 16; o > 0; o >>= 1)
            acc[p] += __shfl_xor_sync(0xffffffffu, acc[p], o);
    if (lane < PP)
        g_wlog[(size_t)t * PP + lane] = acc[lane] + bw[lane];
}

// ---------------------------------------------------------------------------
// Pointwise: clip base, temporal transport, softmax over P, aggregate -> bf16
// ---------------------------------------------------------------------------
__global__ __launch_bounds__(128)
void pointwise_kernel()
{
    const int t   = blockIdx.x;
    const int bt  = t & (TLEN - 1);
    const int tid = threadIdx.x;

    __shared__ float w[PP];
    if (tid < PP) w[tid] = g_wlog[(size_t)t * PP + tid];
    __syncthreads();
    if (tid == 0) {
        float mx = w[0];
#pragma unroll
        for (int p = 1; p < PP; p++) mx = fmaxf(mx, w[p]);
        float sum = 0.0f;
#pragma unroll
        for (int p = 0; p < PP; p++) { w[p] = __expf(w[p] - mx); sum += w[p]; }
        const float inv = 1.0f / sum;
#pragma unroll
        for (int p = 0; p < PP; p++) w[p] *= inv;
    }
    __syncthreads();

    float out = 0.0f;
    if (tid < DD) {
        const int d = tid;
        const float* bc = g_bf + (size_t)t * DBOT;
        if (bt == 0) {
#pragma unroll
            for (int p = 0; p < PP; p++) {
                float c = fminf(fmaxf(bc[p * DD + d], -10.0f), 10.0f);
                out += w[p] * c;
            }
        } else {
            const float* bp = g_bf + (size_t)(t - 1) * DBOT;
#pragma unroll
            for (int p = 0; p < PP; p++) {
                float c  = fminf(fmaxf(bc[p * DD + d], -10.0f), 10.0f);
                float pv = fminf(fmaxf(bp[p * DD + d], -10.0f), 10.0f);
                out += w[p] * (0.9f * c + 0.1f * pv);
            }
        }
    } else {
        const int kd = tid - DD;
        const float* f = g_bf + (size_t)t * DBOT + 512;
#pragma unroll
        for (int p = 0; p < PP; p++)
            out += w[p] * f[p * DD + kd];
    }
    g_comb_bf[(size_t)t * COMBDIM + tid] = __float2bfloat16(out);
}

// ---------------------------------------------------------------------------
// Inputs: 0:x 1:Wi 2:bi 3:Wb 4:bb 5:Wf 6:bf 7:Wl 8:bl 9:Ww 10:bw
//         11:Wm 12:bm 13:Ws 14:bs 15:Wu 16:bu 17:Wo 18:bo
// ---------------------------------------------------------------------------
static const int SMEM_DYN = 3 * 65536 + 1024;   // 3-stage ring (64KB/stage) + pad

extern "C" void kernel_launch(void* const* d_in, const int* in_sizes, int n_in,
                              void* d_out, int out_size)
{
    const float* x  = (const float*)d_in[0];
    const float* Wi = (const float*)d_in[1];
    const float* bi = (const float*)d_in[2];
    const float* Wb = (const float*)d_in[3];
    const float* bb = (const float*)d_in[4];
    const float* Wf = (const float*)d_in[5];
    const float* bf = (const float*)d_in[6];
    const float* Ww = (const float*)d_in[9];
    const float* bw = (const float*)d_in[10];
    const float* Wo = (const float*)d_in[17];
    const float* bo = (const float*)d_in[18];
    float* out = (float*)d_out;

    float *hbot, *bfc, *b23;
    __nv_bfloat16 *combbf, *wiT, *w23T, *woT;
    cudaGetSymbolAddress((void**)&hbot,   g_hbot);
    cudaGetSymbolAddress((void**)&bfc,    g_bf);
    cudaGetSymbolAddress((void**)&combbf, g_comb_bf);
    cudaGetSymbolAddress((void**)&wiT,    g_wiT);
    cudaGetSymbolAddress((void**)&w23T,   g_w23T);
    cudaGetSymbolAddress((void**)&woT,    g_woT);
    cudaGetSymbolAddress((void**)&b23,    g_bias23);

    cudaFuncSetAttribute(mma_gemm<1,1>, cudaFuncAttributeMaxDynamicSharedMemorySize, SMEM_DYN);
    cudaFuncSetAttribute(mma_gemm<2,0>, cudaFuncAttributeMaxDynamicSharedMemorySize, SMEM_DYN);

    // 0) weight prep (all transposes/casts + bias concat)
    weightprep_kernel<<<5633, 256>>>(Wi, Wb, Wf, Wo, bb, bf);

    // 1) GEMM1: h_bot = x @ Wi + bi   [8192,1024], K=4096  (A fp32, fused cast)
    mma_gemm<1,1><<<dim3(DBOT / 256, MTOK / 256), 256, SMEM_DYN>>>(
        x, wiT, bi, nullptr, hbot, DBOT, HDIM);

    // 2) w_logits (fp32)
    wlog_kernel<<<MTOK / 8, 256>>>(Ww, bw);

    // 3) GEMM23: base|fiber = h_bot @ [Wb|Wf] + bias  [8192,1024], K=1024  (A fp32)
    mma_gemm<1,1><<<dim3(DBOT / 256, MTOK / 256), 256, SMEM_DYN>>>(
        hbot, w23T, b23, nullptr, bfc, DBOT, DBOT);

    // 4) pointwise: softmax / transport / aggregate -> combined bf16
    pointwise_kernel<<<MTOK, 128>>>();

    // 5) GEMM4: out = x + combined @ Wo + bo  [8192,4096], K=128  (A bf16)
    mma_gemm<2,0><<<dim3(HDIM / 256, MTOK / 256), 256, SMEM_DYN>>>(
        combbf, woT, bo, x, out, HDIM, COMBDIM);
}

// round 14
// speedup vs baseline: 1.7548x; 1.7548x over previous
#include <cuda_runtime.h>
#include <cuda_bf16.h>
#include <cstdint>

// Problem constants (fixed by the reference setup)
#define MTOK 8192      // B*T
#define TLEN 2048
#define HDIM 4096
#define DBOT 1024
#define PP   8
#define DD   64
#define COMBDIM 128

// Does this compilation pass support tcgen05 (sm_103a arch-specific)?
#if defined(__CUDA_ARCH__) && (defined(__CUDA_ARCH_FEAT_SM103_ALL) || defined(__CUDA_ARCH_SPECIFIC__))
#define HAS_TCGEN05 1
#else
#define HAS_TCGEN05 0
#endif

// ---------------- scratch (device globals) ---------------------------------
__device__ float          g_hbot   [(size_t)MTOK * DBOT];      // fp32 h_bot (for wlog)
__device__ __nv_bfloat16  g_hbot_bf[(size_t)MTOK * DBOT];      // bf16 h_bot (GEMM23 A)
__device__ float          g_bf     [(size_t)MTOK * DBOT];      // base|fiber [8192,1024]
__device__ float          g_wlog   [(size_t)MTOK * PP];
__device__ __nv_bfloat16  g_comb_bf[(size_t)MTOK * COMBDIM];
__device__ __nv_bfloat16  g_xbf    [(size_t)MTOK * HDIM];
__device__ __nv_bfloat16  g_wiT    [(size_t)DBOT * HDIM];      // Wi^T  [1024,4096]
__device__ __nv_bfloat16  g_w23T   [(size_t)DBOT * DBOT];      // [Wb|Wf]^T [1024,1024]
__device__ __nv_bfloat16  g_woT    [(size_t)HDIM * COMBDIM];   // Wo^T  [4096,128]
__device__ float          g_bias23 [DBOT];

// ---------------- common PTX helpers (sm_80+) ------------------------------
__device__ __forceinline__ uint32_t smem_u32(const void* p) {
    uint32_t a;
    asm("{ .reg .u64 t; cvta.to.shared.u64 t, %1; cvt.u32.u64 %0, t; }" : "=r"(a) : "l"(p));
    return a;
}
__device__ __forceinline__ void cp16(uint32_t s, const void* g) {
    asm volatile("cp.async.cg.shared.global [%0], [%1], 16;" :: "r"(s), "l"(g));
}
__device__ __forceinline__ void cp_commit() { asm volatile("cp.async.commit_group;"); }
__device__ __forceinline__ void cp_wait0()  { asm volatile("cp.async.wait_group 0;"); }
__device__ __forceinline__ void cp_wait1()  { asm volatile("cp.async.wait_group 1;"); }

__device__ __forceinline__ void ldm_x4(uint32_t& r0, uint32_t& r1, uint32_t& r2, uint32_t& r3,
                                       uint32_t addr) {
    asm volatile("ldmatrix.sync.aligned.m8n8.x4.shared.b16 {%0,%1,%2,%3}, [%4];"
                 : "=r"(r0), "=r"(r1), "=r"(r2), "=r"(r3) : "r"(addr));
}
__device__ __forceinline__ void mma_bf16(float* d, const uint32_t* a, const uint32_t* b) {
    asm volatile("mma.sync.aligned.m16n8k16.row.col.f32.bf16.bf16.f32 "
                 "{%0,%1,%2,%3}, {%4,%5,%6,%7}, {%8,%9}, {%0,%1,%2,%3};"
                 : "+f"(d[0]), "+f"(d[1]), "+f"(d[2]), "+f"(d[3])
                 : "r"(a[0]), "r"(a[1]), "r"(a[2]), "r"(a[3]), "r"(b[0]), "r"(b[1]));
}
__device__ __forceinline__ uint32_t swz(uint32_t o) { return o ^ ((o >> 3) & 0x70u); }

// ---------------- tcgen05 helpers (sm_103a pass only) ----------------------
#if HAS_TCGEN05
__device__ __forceinline__ uint32_t elect_one() {
    uint32_t pred;
    asm volatile("{\n\t.reg .pred p;\n\telect.sync _|p, 0xFFFFFFFF;\n\t"
                 "selp.b32 %0, 1, 0, p;\n\t}" : "=r"(pred));
    return pred;
}
__device__ __forceinline__ void mbar_init(uint32_t a, uint32_t cnt) {
    asm volatile("mbarrier.init.shared.b64 [%0], %1;" :: "r"(a), "r"(cnt) : "memory");
}
__device__ __forceinline__ void mbar_wait(uint32_t a, uint32_t parity) {
    uint32_t done;
    do {
        asm volatile("{\n\t.reg .pred p;\n\t"
            "mbarrier.try_wait.parity.acquire.cta.shared::cta.b64 p, [%1], %2, 0x989680;\n\t"
            "selp.b32 %0, 1, 0, p;\n\t}"
            : "=r"(done) : "r"(a), "r"(parity) : "memory");
    } while (!done);
}
// .noinc is load-bearing (R10 deadlock post-mortem): it consumes a preset
// expected arrival; the default form is net-zero against the init count.
__device__ __forceinline__ void cp_mbar_arrive_noinc(uint32_t a) {
    asm volatile("cp.async.mbarrier.arrive.noinc.shared::cta.b64 [%0];" :: "r"(a) : "memory");
}
__device__ __forceinline__ void tmem_alloc(uint32_t smem_dst, uint32_t ncols) {
    asm volatile("tcgen05.alloc.cta_group::1.sync.aligned.shared::cta.b32 [%0], %1;"
                 :: "r"(smem_dst), "r"(ncols) : "memory");
}
__device__ __forceinline__ void tmem_dealloc(uint32_t tmem, uint32_t ncols) {
    asm volatile("tcgen05.relinquish_alloc_permit.cta_group::1.sync.aligned;");
    asm volatile("tcgen05.dealloc.cta_group::1.sync.aligned.b32 %0, %1;" :: "r"(tmem), "r"(ncols));
}
__device__ __forceinline__ void mma_f16_ss(uint32_t d, uint64_t adesc, uint64_t bdesc,
                                           uint32_t idesc, uint32_t enable) {
    asm volatile("{\n\t.reg .pred p;\n\tsetp.ne.u32 p, %4, 0;\n\t"
        "tcgen05.mma.cta_group::1.kind::f16 [%0], %1, %2, %3, {%5, %5, %5, %5}, p;\n\t}"
        :: "r"(d), "l"(adesc), "l"(bdesc), "r"(idesc), "r"(enable), "r"(0u) : "memory");
}
__device__ __forceinline__ void mma_commit(uint32_t mbar) {
    asm volatile("tcgen05.commit.cta_group::1.mbarrier::arrive::one.shared::cluster.b64 [%0];"
                 :: "r"(mbar) : "memory");
}
__device__ __forceinline__ void ldtm_x32(uint32_t* r, uint32_t tmem) {
    asm volatile("tcgen05.ld.sync.aligned.32x32b.x32.b32 "
        "{%0,%1,%2,%3,%4,%5,%6,%7,%8,%9,%10,%11,%12,%13,%14,%15,"
        "%16,%17,%18,%19,%20,%21,%22,%23,%24,%25,%26,%27,%28,%29,%30,%31}, [%32];"
        : "=r"(r[0]),"=r"(r[1]),"=r"(r[2]),"=r"(r[3]),"=r"(r[4]),"=r"(r[5]),"=r"(r[6]),"=r"(r[7]),
          "=r"(r[8]),"=r"(r[9]),"=r"(r[10]),"=r"(r[11]),"=r"(r[12]),"=r"(r[13]),"=r"(r[14]),"=r"(r[15]),
          "=r"(r[16]),"=r"(r[17]),"=r"(r[18]),"=r"(r[19]),"=r"(r[20]),"=r"(r[21]),"=r"(r[22]),"=r"(r[23]),
          "=r"(r[24]),"=r"(r[25]),"=r"(r[26]),"=r"(r[27]),"=r"(r[28]),"=r"(r[29]),"=r"(r[30]),"=r"(r[31])
        : "r"(tmem));
}
__device__ __forceinline__ void tmem_wait_ld()  { asm volatile("tcgen05.wait::ld.sync.aligned;" ::: "memory"); }
__device__ __forceinline__ void tc_fence_after(){ asm volatile("tcgen05.fence::after_thread_sync;" ::: "memory"); }

static constexpr uint64_t DESC_BASE_SW128 =
    (uint64_t(2) << 61) | (uint64_t(1) << 46) | (uint64_t(64) << 32) | (uint64_t(1) << 16);
__device__ __forceinline__ uint64_t mk_desc(uint32_t addr) {
    return DESC_BASE_SW128 | ((uint64_t)(addr >> 4) & 0x3FFFull);
}
// idesc: kind::f16, dtype=F32, atype=btype=BF16, M=128, N=128
static constexpr uint32_t IDESC =
    (1u << 4) | (1u << 7) | (1u << 10) | ((128u / 8) << 17) | ((128u / 16) << 24);
#endif  // HAS_TCGEN05

// ---------------------------------------------------------------------------
// bf16 tensor-core GEMM: C[M,N] = A[M,K](bf16 K-major) @ Bw[N,K](bf16 K-major)^T
// CTA tile 256x256, BK=64, 256 threads. (R12 committed design — cp.async only.)
//  - sm_103a pass: WARP-SPECIALIZED tcgen05 pipeline:
//      warps 0-3 producers (cp.async + cp.async.mbarrier.arrive.noinc -> full[b]),
//      warp 4 elect: full-wait -> 16 MMA atoms -> commit empty[b],
//      3-stage 64KB ring, no __syncthreads in the mainloop.
//  - generic pass: mma.sync (HMMA), four 128x128 quadrants (never runs)
// MODE 0: C -> Cf(fp32) and Cbf(bf16), +bias
// MODE 1: C -> Cf, +bias
// MODE 2: C -> Cf, +bias +res
// ---------------------------------------------------------------------------
#define STAGE_BYTES 65536u     // A0(16K) A1(16K) B0(16K) B1(16K)

template<int MODE>
__global__ __launch_bounds__(256)
void mma_gemm(const __nv_bfloat16* __restrict__ A,
              const __nv_bfloat16* __restrict__ Bw,
              const float* __restrict__ bias,
              const float* __restrict__ res,
              float* __restrict__ Cf,
              __nv_bfloat16* __restrict__ Cbf,
              int N, int K)
{
#if HAS_TCGEN05
    // ============ tcgen05 warp-specialized pipeline =========================
    extern __shared__ char dsm[];
    __shared__ uint32_t s_tmem;
    __shared__ __align__(8) uint64_t s_full[3], s_empty[3], s_fin;

    const int tid = threadIdx.x;
    const int wid = tid >> 5;
    const int lid = tid & 31;
    const int n0 = blockIdx.x * 256;
    const int m0 = blockIdx.y * 256;

    const uint32_t tile0 = (smem_u32(dsm) + 1023u) & ~1023u;
    uint32_t fullb[3], emptyb[3];
#pragma unroll
    for (int b = 0; b < 3; b++) {
        fullb[b]  = smem_u32(&s_full[b]);
        emptyb[b] = smem_u32(&s_empty[b]);
    }
    const uint32_t finb = smem_u32(&s_fin);

    if (wid == 0) tmem_alloc(smem_u32(&s_tmem), 512);
    if (tid == 0) {
#pragma unroll
        for (int b = 0; b < 3; b++) { mbar_init(fullb[b], 128); mbar_init(emptyb[b], 1); }
        mbar_init(finb, 1);
    }
    __syncthreads();
    uint32_t tmem;
    asm volatile("ld.shared.b32 %0, [%1];" : "=r"(tmem) : "r"(smem_u32(&s_tmem)));

    const int steps = K >> 6;

    if (tid < 128) {
        // ---------------- producers (warps 0-3) ----------------------------
        // Stage = 512 rows x 128B (A rows 0-255, B rows 256-511).
        // thread t: rt = t>>3 (0..15), off = (t&7)*16; 32 chunks of 16B.
        const int rt  = tid >> 3;
        const int off = (tid & 7) * 16;
        const uint32_t soff = (uint32_t)(off ^ ((rt & 7) << 4));
        const __nv_bfloat16* Abase = A  + (size_t)(m0 + rt) * K + (off >> 1);
        const __nv_bfloat16* Bbase = Bw + (size_t)(n0 + rt) * K + (off >> 1);

        int php[3] = {0, 0, 0};
        for (int c = 0; c < steps; c++) {
            const int b = c % 3;
            if (c >= 3) { mbar_wait(emptyb[b], php[b]); php[b] ^= 1; }
            const uint32_t sbase = tile0 + (uint32_t)b * STAGE_BYTES;
            const __nv_bfloat16* ag = Abase + c * 64;
            const __nv_bfloat16* bg = Bbase + c * 64;
#pragma unroll
            for (int j = 0; j < 16; j++)
                cp16(sbase + (uint32_t)(j * 16 + rt) * 128u + soff,
                     ag + (size_t)j * 16 * K);
#pragma unroll
            for (int j = 0; j < 16; j++)
                cp16(sbase + (uint32_t)(256 + j * 16 + rt) * 128u + soff,
                     bg + (size_t)j * 16 * K);
            cp_mbar_arrive_noinc(fullb[b]);   // arrives when this thread's cps land
        }
    } else if (wid == 4) {
        // ---------------- MMA issuer (warp 4, one thread) -------------------
        if (elect_one()) {
            int phm[3] = {0, 0, 0};
            for (int c = 0; c < steps; c++) {
                const int b = c % 3;
                mbar_wait(fullb[b], phm[b]); phm[b] ^= 1;
                const uint32_t sbase = tile0 + (uint32_t)b * STAGE_BYTES;
                const uint64_t ad0 = mk_desc(sbase);
                const uint64_t ad1 = mk_desc(sbase + 16384u);
                const uint64_t bd0 = mk_desc(sbase + 32768u);
                const uint64_t bd1 = mk_desc(sbase + 49152u);
#pragma unroll
                for (int ss = 0; ss < 4; ss++) {
                    const uint32_t en = (c > 0 || ss > 0) ? 1u : 0u;
                    mma_f16_ss(tmem,       ad0 + ss * 2, bd0 + ss * 2, IDESC, en);
                    mma_f16_ss(tmem + 128, ad1 + ss * 2, bd0 + ss * 2, IDESC, en);
                    mma_f16_ss(tmem + 256, ad0 + ss * 2, bd1 + ss * 2, IDESC, en);
                    mma_f16_ss(tmem + 384, ad1 + ss * 2, bd1 + ss * 2, IDESC, en);
                }
                mma_commit(emptyb[b]);    // buffer reusable when these MMAs finish
            }
            mma_commit(finb);             // all MMAs done
        }
    }
    // warps 5-7 fall through to the epilogue barrier

    __syncthreads();
    mbar_wait(finb, 0);
    tc_fence_after();

    // epilogue: warps 0-3 -> m-half 0 (rows m0+wid*32+lid), warps 4-7 -> m-half 1.
    // atom(mh,nh) at tmem + mh*128 + nh*256; 8 column chunks of 32.
    const int row = m0 + wid * 32 + lid;
    const uint32_t dm = tmem + (uint32_t)((wid >> 2) * 128);
#pragma unroll
    for (int nb = 0; nb < 8; nb++) {
        uint32_t r[32];
        ldtm_x32(r, dm + (uint32_t)((nb >> 2) * 256 + (nb & 3) * 32));
        tmem_wait_ld();
#pragma unroll
        for (int j = 0; j < 32; j += 4) {
            const int n = n0 + nb * 32 + j;
            float4 bv = *reinterpret_cast<const float4*>(bias + n);
            float4 v;
            v.x = __uint_as_float(r[j + 0]) + bv.x;
            v.y = __uint_as_float(r[j + 1]) + bv.y;
            v.z = __uint_as_float(r[j + 2]) + bv.z;
            v.w = __uint_as_float(r[j + 3]) + bv.w;
            if (MODE == 2) {
                float4 rv = *reinterpret_cast<const float4*>(res + (size_t)row * N + n);
                v.x += rv.x; v.y += rv.y; v.z += rv.z; v.w += rv.w;
            }
            *reinterpret_cast<float4*>(Cf + (size_t)row * N + n) = v;
            if (MODE == 0) {
                __nv_bfloat162* cb = reinterpret_cast<__nv_bfloat162*>(Cbf + (size_t)row * N + n);
                cb[0] = __nv_bfloat162(__float2bfloat16(v.x), __float2bfloat16(v.y));
                cb[1] = __nv_bfloat162(__float2bfloat16(v.z), __float2bfloat16(v.w));
            }
        }
    }

    __syncthreads();
    if (wid == 0) tmem_dealloc(tmem, 512);

#else
    // ============ mma.sync fallback: four 128x128 quadrants (never runs) ====
    extern __shared__ char dsm[];
    const uint32_t tile0 = (smem_u32(dsm) + 1023u) & ~1023u;

    const int tid  = threadIdx.x;
    const int lane = tid & 31;
    const int wid  = tid >> 5;
    const int wm   = wid & 3;
    const int wn   = wid >> 2;

    const int ldr = tid >> 1;
    const int ldc = (tid & 1) * 4;

    const int grp = lane >> 3;
    const int l7  = lane & 7;
    const uint32_t a_row = (uint32_t)((grp & 1) * 8 + l7);
    const uint32_t a_kb  = (uint32_t)((grp >> 1) * 16);
    const uint32_t b_row = (uint32_t)((grp >> 1) * 8 + l7);
    const uint32_t b_kb  = (uint32_t)((grp & 1) * 16);

    const int steps = K >> 6;

    for (int hm = 0; hm < 2; hm++)
    for (int hn = 0; hn < 2; hn++) {
        const int m0 = blockIdx.y * 256 + hm * 128;
        const int n0 = blockIdx.x * 256 + hn * 128;

        float acc[2][8][4];
#pragma unroll
        for (int i = 0; i < 2; i++)
#pragma unroll
            for (int j = 0; j < 8; j++)
#pragma unroll
                for (int v = 0; v < 4; v++) acc[i][j][v] = 0.0f;

        auto load_stage = [&](int c) {
            const uint32_t sb = tile0 + (uint32_t)(c & 1) * 32768u;
            const __nv_bfloat16* ag = A  + (size_t)(m0 + ldr) * K + c * 64;
            const __nv_bfloat16* bg = Bw + (size_t)(n0 + ldr) * K + c * 64;
#pragma unroll
            for (int g = 0; g < 4; g++) {
                const uint32_t co = (uint32_t)(ldc + g) * 16u;
                cp16(sb + swz((uint32_t)ldr * 128u + co),            ag + (ldc + g) * 8);
                cp16(sb + 16384u + swz((uint32_t)ldr * 128u + co),   bg + (ldc + g) * 8);
            }
            cp_commit();
        };

        load_stage(0);
        if (steps > 1) load_stage(1);

        for (int s = 0; s < steps; s++) {
            if (s + 2 <= steps) cp_wait1(); else cp_wait0();
            __syncthreads();

            const uint32_t sA = tile0 + (uint32_t)(s & 1) * 32768u;
            const uint32_t sB = sA + 16384u;

#pragma unroll
            for (int ks = 0; ks < 4; ks++) {
                const uint32_t kbase = (uint32_t)ks * 32u;
                uint32_t af[2][4];
#pragma unroll
                for (int mt = 0; mt < 2; mt++) {
                    const uint32_t r = (uint32_t)(wm * 32 + mt * 16) + a_row;
                    ldm_x4(af[mt][0], af[mt][1], af[mt][2], af[mt][3],
                           sA + swz(r * 128u + kbase + a_kb));
                }
                uint32_t bf_[8][2];
#pragma unroll
                for (int nt2 = 0; nt2 < 4; nt2++) {
                    const uint32_t r = (uint32_t)(wn * 64 + nt2 * 16) + b_row;
                    uint32_t r0, r1, r2, r3;
                    ldm_x4(r0, r1, r2, r3, sB + swz(r * 128u + kbase + b_kb));
                    bf_[nt2 * 2 + 0][0] = r0; bf_[nt2 * 2 + 0][1] = r1;
                    bf_[nt2 * 2 + 1][0] = r2; bf_[nt2 * 2 + 1][1] = r3;
                }
#pragma unroll
                for (int mt = 0; mt < 2; mt++)
#pragma unroll
                    for (int nt = 0; nt < 8; nt++)
                        mma_bf16(acc[mt][nt], af[mt], bf_[nt]);
            }

            __syncthreads();
            if (s + 2 < steps) load_stage(s + 2);
        }

#pragma unroll
        for (int mt = 0; mt < 2; mt++) {
            const int rbase = m0 + wm * 32 + mt * 16 + (lane >> 2);
#pragma unroll
            for (int nt = 0; nt < 8; nt++) {
                const int col = n0 + wn * 64 + nt * 8 + 2 * (lane & 3);
                const float2 bv = *reinterpret_cast<const float2*>(bias + col);
#pragma unroll
                for (int h = 0; h < 2; h++) {
                    const int row = rbase + h * 8;
                    float2 v;
                    v.x = acc[mt][nt][h * 2 + 0] + bv.x;
                    v.y = acc[mt][nt][h * 2 + 1] + bv.y;
                    if (MODE == 2) {
                        float2 rv = *reinterpret_cast<const float2*>(res + (size_t)row * N + col);
                        v.x += rv.x; v.y += rv.y;
                    }
                    *reinterpret_cast<float2*>(Cf + (size_t)row * N + col) = v;
                    if (MODE == 0) {
                        *reinterpret_cast<__nv_bfloat162*>(Cbf + (size_t)row * N + col) =
                            __nv_bfloat162(__float2bfloat16(v.x), __float2bfloat16(v.y));
                    }
                }
            }
        }
        __syncthreads();
    }
#endif
}

// ---------------------------------------------------------------------------
// castx: fp32 x -> bf16 xbf (vectorized)
// ---------------------------------------------------------------------------
__global__ __launch_bounds__(256)
void castx_kernel(const float* __restrict__ in, __nv_bfloat16* __restrict__ out)
{
    const size_t i = (size_t)blockIdx.x * 256 + threadIdx.x;   // float4 index
    float4 v = reinterpret_cast<const float4*>(in)[i];
    __nv_bfloat162* o = reinterpret_cast<__nv_bfloat162*>(out) + i * 2;
    o[0] = __nv_bfloat162(__float2bfloat16(v.x), __float2bfloat16(v.y));
    o[1] = __nv_bfloat162(__float2bfloat16(v.z), __float2bfloat16(v.w));
}

// ---------------------------------------------------------------------------
// weightprep: all weight transposes/casts + bias concat in ONE kernel.
//  blocks [0,4096):    Wi [4096,1024] -> wiT [1024,4096]
//  blocks [4096,4608): Wb [1024,512]  -> w23T rows [0,512)
//  blocks [4608,5120): Wf [1024,512]  -> w23T rows [512,1024)
//  blocks [5120,5632): Wo [128,4096]  -> woT [4096,128]
//  block  5632:        bias23 = [bb|bf]
// ---------------------------------------------------------------------------
__global__ __launch_bounds__(256)
void weightprep_kernel(const float* __restrict__ Wi, const float* __restrict__ Wb,
                       const float* __restrict__ Wf, const float* __restrict__ Wo,
                       const float* __restrict__ bb, const float* __restrict__ bf)
{
    __shared__ float t[32][33];
    const int id = blockIdx.x;

    const float* in; __nv_bfloat16* out; int K, N, n0, k0;
    if (id < 4096)      { in = Wi; out = g_wiT;  K = HDIM;    N = DBOT; n0 = (id & 31) * 32;  k0 = (id >> 5) * 32; }
    else if (id < 4608) { int l = id - 4096; in = Wb; out = g_w23T; K = DBOT; N = 512; n0 = (l & 15) * 32; k0 = (l >> 4) * 32; }
    else if (id < 5120) { int l = id - 4608; in = Wf; out = g_w23T + (size_t)512 * DBOT; K = DBOT; N = 512; n0 = (l & 15) * 32; k0 = (l >> 4) * 32; }
    else if (id < 5632) { int l = id - 5120; in = Wo; out = g_woT;  K = COMBDIM; N = HDIM; n0 = (l & 127) * 32; k0 = (l >> 7) * 32; }
    else {
        for (int i = threadIdx.x; i < 512; i += 256) {
            g_bias23[i]       = bb[i];
            g_bias23[i + 512] = bf[i];
        }
        return;
    }

    const int tx = threadIdx.x & 31, ty = threadIdx.x >> 5;   // 32 x 8
#pragma unroll
    for (int i = 0; i < 32; i += 8)
        t[ty + i][tx] = in[(size_t)(k0 + ty + i) * N + n0 + tx];
    __syncthreads();
#pragma unroll
    for (int i = 0; i < 32; i += 8)
        out[(size_t)(n0 + ty + i) * K + k0 + tx] = __float2bfloat16(t[tx][ty + i]);
}

// ---------------------------------------------------------------------------
// w_logits (fp32, reads fp32 h_bot): warp per token, coalesced Ww rows
// ---------------------------------------------------------------------------
__global__ __launch_bounds__(256)
void wlog_kernel(const float* __restrict__ Ww, const float* __restrict__ bw)
{
    const int warp = threadIdx.x >> 5;
    const int lane = threadIdx.x & 31;
    const int t = blockIdx.x * 8 + warp;
    const float* h = g_hbot + (size_t)t * DBOT;

    float acc[PP];
#pragma unroll
    for (int p = 0; p < PP; p++) acc[p] = 0.0f;
#pragma unroll 4
    for (int k = lane; k < DBOT; k += 32) {
        const float hv = h[k];
        float4 w0 = *reinterpret_cast<const float4*>(Ww + (size_t)k * PP);
        float4 w1 = *reinterpret_cast<const float4*>(Ww + (size_t)k * PP + 4);
        acc[0] = fmaf(hv, w0.x, acc[0]); acc[1] = fmaf(hv, w0.y, acc[1]);
        acc[2] = fmaf(hv, w0.z, acc[2]); acc[3] = fmaf(hv, w0.w, acc[3]);
        acc[4] = fmaf(hv, w1.x, acc[4]); acc[5] = fmaf(hv, w1.y, acc[5]);
        acc[6] = fmaf(hv, w1.z, acc[6]); acc[7] = fmaf(hv, w1.w, acc[7]);
    }
#pragma unroll
    for (int p = 0; p < PP; p++)
#pragma unroll
        for (int o = 16; o > 0; o >>= 1)
            acc[p] += __shfl_xor_sync(0xffffffffu, acc[p], o);
    if (lane < PP)
        g_wlog[(size_t)t * PP + lane] = acc[lane] + bw[lane];
}

// ---------------------------------------------------------------------------
// Pointwise: clip base, temporal transport, softmax over P, aggregate -> bf16
// ---------------------------------------------------------------------------
__global__ __launch_bounds__(128)
void pointwise_kernel()
{
    const int t   = blockIdx.x;
    const int bt  = t & (TLEN - 1);
    const int tid = threadIdx.x;

    __shared__ float w[PP];
    if (tid < PP) w[tid] = g_wlog[(size_t)t * PP + tid];
    __syncthreads();
    if (tid == 0) {
        float mx = w[0];
#pragma unroll
        for (int p = 1; p < PP; p++) mx = fmaxf(mx, w[p]);
        float sum = 0.0f;
#pragma unroll
        for (int p = 0; p < PP; p++) { w[p] = __expf(w[p] - mx); sum += w[p]; }
        const float inv = 1.0f / sum;
#pragma unroll
        for (int p = 0; p < PP; p++) w[p] *= inv;
    }
    __syncthreads();

    float out = 0.0f;
    if (tid < DD) {
        const int d = tid;
        const float* bc = g_bf + (size_t)t * DBOT;
        if (bt == 0) {
#pragma unroll
            for (int p = 0; p < PP; p++) {
                float c = fminf(fmaxf(bc[p * DD + d], -10.0f), 10.0f);
                out += w[p] * c;
            }
        } else {
            const float* bp = g_bf + (size_t)(t - 1) * DBOT;
#pragma unroll
            for (int p = 0; p < PP; p++) {
                float c  = fminf(fmaxf(bc[p * DD + d], -10.0f), 10.0f);
                float pv = fminf(fmaxf(bp[p * DD + d], -10.0f), 10.0f);
                out += w[p] * (0.9f * c + 0.1f * pv);
            }
        }
    } else {
        const int kd = tid - DD;
        const float* f = g_bf + (size_t)t * DBOT + 512;
#pragma unroll
        for (int p = 0; p < PP; p++)
            out += w[p] * f[p * DD + kd];
    }
    g_comb_bf[(size_t)t * COMBDIM + tid] = __float2bfloat16(out);
}

// ---------------------------------------------------------------------------
// Inputs: 0:x 1:Wi 2:bi 3:Wb 4:bb 5:Wf 6:bf 7:Wl 8:bl 9:Ww 10:bw
//         11:Wm 12:bm 13:Ws 14:bs 15:Wu 16:bu 17:Wo 18:bo
// ---------------------------------------------------------------------------
static const int SMEM_DYN = 3 * 65536 + 1024;   // 3-stage ring (64KB/stage) + pad

extern "C" void kernel_launch(void* const* d_in, const int* in_sizes, int n_in,
                              void* d_out, int out_size)
{
    const float* x  = (const float*)d_in[0];
    const float* Wi = (const float*)d_in[1];
    const float* bi = (const float*)d_in[2];
    const float* Wb = (const float*)d_in[3];
    const float* bb = (const float*)d_in[4];
    const float* Wf = (const float*)d_in[5];
    const float* bf = (const float*)d_in[6];
    const float* Ww = (const float*)d_in[9];
    const float* bw = (const float*)d_in[10];
    const float* Wo = (const float*)d_in[17];
    const float* bo = (const float*)d_in[18];
    float* out = (float*)d_out;

    float *hbot, *bfc, *b23;
    __nv_bfloat16 *hbotbf, *combbf, *xbf, *wiT, *w23T, *woT;
    cudaGetSymbolAddress((void**)&hbot,   g_hbot);
    cudaGetSymbolAddress((void**)&hbotbf, g_hbot_bf);
    cudaGetSymbolAddress((void**)&bfc,    g_bf);
    cudaGetSymbolAddress((void**)&combbf, g_comb_bf);
    cudaGetSymbolAddress((void**)&xbf,    g_xbf);
    cudaGetSymbolAddress((void**)&wiT,    g_wiT);
    cudaGetSymbolAddress((void**)&w23T,   g_w23T);
    cudaGetSymbolAddress((void**)&woT,    g_woT);
    cudaGetSymbolAddress((void**)&b23,    g_bias23);

    cudaFuncSetAttribute(mma_gemm<0>, cudaFuncAttributeMaxDynamicSharedMemorySize, SMEM_DYN);
    cudaFuncSetAttribute(mma_gemm<1>, cudaFuncAttributeMaxDynamicSharedMemorySize, SMEM_DYN);
    cudaFuncSetAttribute(mma_gemm<2>, cudaFuncAttributeMaxDynamicSharedMemorySize, SMEM_DYN);

    // 0) weight prep (all transposes/casts + bias concat, one kernel)
    weightprep_kernel<<<5633, 256>>>(Wi, Wb, Wf, Wo, bb, bf);                     // 0

    // 1) castx: x -> bf16
    castx_kernel<<<(MTOK * HDIM / 4) / 256, 256>>>(x, xbf);                       // 1

    // 2) GEMM1: h_bot = x @ Wi + bi  [8192,1024], K=4096 (dual fp32+bf16 out)
    mma_gemm<0><<<dim3(DBOT / 256, MTOK / 256), 256, SMEM_DYN>>>(                 // 2
        xbf, wiT, bi, nullptr, hbot, hbotbf, DBOT, HDIM);

    // 3) GEMM23: base|fiber = h_bot @ [Wb|Wf] + bias  [8192,1024], K=1024
    //    (launch idx 3 -> ncu captures a GEMM)
    mma_gemm<1><<<dim3(DBOT / 256, MTOK / 256), 256, SMEM_DYN>>>(                 // 3
        hbotbf, w23T, b23, nullptr, bfc, nullptr, DBOT, DBOT);

    // 4) w_logits (fp32)
    wlog_kernel<<<MTOK / 8, 256>>>(Ww, bw);                                       // 4

    // 5) pointwise: softmax / transport / aggregate -> combined bf16
    pointwise_kernel<<<MTOK, 128>>>();                                            // 5

    // 6) GEMM4: out = x + combined @ Wo + bo  [8192,4096], K=128
    mma_gemm<2><<<dim3(HDIM / 256, MTOK / 256), 256, SMEM_DYN>>>(                 // 6
        combbf, woT, bo, x, out, nullptr, HDIM, COMBDIM);
}

// round 15
// speedup vs baseline: 1.8033x; 1.0276x over previous
#include <cuda_runtime.h>
#include <cuda_bf16.h>
#include <cstdint>

// Problem constants (fixed by the reference setup)
#define MTOK 8192      // B*T
#define TLEN 2048
#define HDIM 4096
#define DBOT 1024
#define PP   8
#define DD   64
#define COMBDIM 128

// Does this compilation pass support tcgen05 (sm_103a arch-specific)?
#if defined(__CUDA_ARCH__) && (defined(__CUDA_ARCH_FEAT_SM103_ALL) || defined(__CUDA_ARCH_SPECIFIC__))
#define HAS_TCGEN05 1
#else
#define HAS_TCGEN05 0
#endif

// ---------------- scratch (device globals) ---------------------------------
__device__ float          g_hbot   [(size_t)MTOK * DBOT];      // fp32 h_bot (for wlog)
__device__ __nv_bfloat16  g_hbot_bf[(size_t)MTOK * DBOT];      // bf16 h_bot (GEMM23 A)
__device__ float          g_bf     [(size_t)MTOK * DBOT];      // base|fiber [8192,1024]
__device__ float          g_wlog   [(size_t)MTOK * PP];
__device__ __nv_bfloat16  g_comb_bf[(size_t)MTOK * COMBDIM];
__device__ __nv_bfloat16  g_xbf    [(size_t)MTOK * HDIM];
__device__ __nv_bfloat16  g_wiT    [(size_t)DBOT * HDIM];      // Wi^T  [1024,4096]
__device__ __nv_bfloat16  g_w23T   [(size_t)DBOT * DBOT];      // [Wb|Wf]^T [1024,1024]
__device__ __nv_bfloat16  g_woT    [(size_t)HDIM * COMBDIM];   // Wo^T  [4096,128]
__device__ float          g_bias23 [DBOT];

// ---------------- common PTX helpers (sm_80+) ------------------------------
__device__ __forceinline__ uint32_t smem_u32(const void* p) {
    uint32_t a;
    asm("{ .reg .u64 t; cvta.to.shared.u64 t, %1; cvt.u32.u64 %0, t; }" : "=r"(a) : "l"(p));
    return a;
}
__device__ __forceinline__ void cp16(uint32_t s, const void* g) {
    asm volatile("cp.async.cg.shared.global [%0], [%1], 16;" :: "r"(s), "l"(g));
}
__device__ __forceinline__ void cp_commit() { asm volatile("cp.async.commit_group;"); }
__device__ __forceinline__ void cp_wait0()  { asm volatile("cp.async.wait_group 0;"); }
__device__ __forceinline__ void cp_wait1()  { asm volatile("cp.async.wait_group 1;"); }

__device__ __forceinline__ void ldm_x4(uint32_t& r0, uint32_t& r1, uint32_t& r2, uint32_t& r3,
                                       uint32_t addr) {
    asm volatile("ldmatrix.sync.aligned.m8n8.x4.shared.b16 {%0,%1,%2,%3}, [%4];"
                 : "=r"(r0), "=r"(r1), "=r"(r2), "=r"(r3) : "r"(addr));
}
__device__ __forceinline__ void mma_bf16(float* d, const uint32_t* a, const uint32_t* b) {
    asm volatile("mma.sync.aligned.m16n8k16.row.col.f32.bf16.bf16.f32 "
                 "{%0,%1,%2,%3}, {%4,%5,%6,%7}, {%8,%9}, {%0,%1,%2,%3};"
                 : "+f"(d[0]), "+f"(d[1]), "+f"(d[2]), "+f"(d[3])
                 : "r"(a[0]), "r"(a[1]), "r"(a[2]), "r"(a[3]), "r"(b[0]), "r"(b[1]));
}
__device__ __forceinline__ uint32_t swz(uint32_t o) { return o ^ ((o >> 3) & 0x70u); }

// ---------------- tcgen05 helpers (sm_103a pass only) ----------------------
#if HAS_TCGEN05
__device__ __forceinline__ uint32_t elect_one() {
    uint32_t pred;
    asm volatile("{\n\t.reg .pred p;\n\telect.sync _|p, 0xFFFFFFFF;\n\t"
                 "selp.b32 %0, 1, 0, p;\n\t}" : "=r"(pred));
    return pred;
}
__device__ __forceinline__ void mbar_init(uint32_t a, uint32_t cnt) {
    asm volatile("mbarrier.init.shared.b64 [%0], %1;" :: "r"(a), "r"(cnt) : "memory");
}
__device__ __forceinline__ void mbar_wait(uint32_t a, uint32_t parity) {
    uint32_t done;
    do {
        asm volatile("{\n\t.reg .pred p;\n\t"
            "mbarrier.try_wait.parity.acquire.cta.shared::cta.b64 p, [%1], %2, 0x989680;\n\t"
            "selp.b32 %0, 1, 0, p;\n\t}"
            : "=r"(done) : "r"(a), "r"(parity) : "memory");
    } while (!done);
}
// .noinc is load-bearing (R10 deadlock post-mortem): it consumes a preset
// expected arrival; the default form is net-zero against the init count.
__device__ __forceinline__ void cp_mbar_arrive_noinc(uint32_t a) {
    asm volatile("cp.async.mbarrier.arrive.noinc.shared::cta.b64 [%0];" :: "r"(a) : "memory");
}
__device__ __forceinline__ void tmem_alloc(uint32_t smem_dst, uint32_t ncols) {
    asm volatile("tcgen05.alloc.cta_group::1.sync.aligned.shared::cta.b32 [%0], %1;"
                 :: "r"(smem_dst), "r"(ncols) : "memory");
}
__device__ __forceinline__ void tmem_dealloc(uint32_t tmem, uint32_t ncols) {
    asm volatile("tcgen05.relinquish_alloc_permit.cta_group::1.sync.aligned;");
    asm volatile("tcgen05.dealloc.cta_group::1.sync.aligned.b32 %0, %1;" :: "r"(tmem), "r"(ncols));
}
__device__ __forceinline__ void mma_f16_ss(uint32_t d, uint64_t adesc, uint64_t bdesc,
                                           uint32_t idesc, uint32_t enable) {
    asm volatile("{\n\t.reg .pred p;\n\tsetp.ne.u32 p, %4, 0;\n\t"
        "tcgen05.mma.cta_group::1.kind::f16 [%0], %1, %2, %3, {%5, %5, %5, %5}, p;\n\t}"
        :: "r"(d), "l"(adesc), "l"(bdesc), "r"(idesc), "r"(enable), "r"(0u) : "memory");
}
__device__ __forceinline__ void mma_commit(uint32_t mbar) {
    asm volatile("tcgen05.commit.cta_group::1.mbarrier::arrive::one.shared::cluster.b64 [%0];"
                 :: "r"(mbar) : "memory");
}
__device__ __forceinline__ void ldtm_x32(uint32_t* r, uint32_t tmem) {
    asm volatile("tcgen05.ld.sync.aligned.32x32b.x32.b32 "
        "{%0,%1,%2,%3,%4,%5,%6,%7,%8,%9,%10,%11,%12,%13,%14,%15,"
        "%16,%17,%18,%19,%20,%21,%22,%23,%24,%25,%26,%27,%28,%29,%30,%31}, [%32];"
        : "=r"(r[0]),"=r"(r[1]),"=r"(r[2]),"=r"(r[3]),"=r"(r[4]),"=r"(r[5]),"=r"(r[6]),"=r"(r[7]),
          "=r"(r[8]),"=r"(r[9]),"=r"(r[10]),"=r"(r[11]),"=r"(r[12]),"=r"(r[13]),"=r"(r[14]),"=r"(r[15]),
          "=r"(r[16]),"=r"(r[17]),"=r"(r[18]),"=r"(r[19]),"=r"(r[20]),"=r"(r[21]),"=r"(r[22]),"=r"(r[23]),
          "=r"(r[24]),"=r"(r[25]),"=r"(r[26]),"=r"(r[27]),"=r"(r[28]),"=r"(r[29]),"=r"(r[30]),"=r"(r[31])
        : "r"(tmem));
}
__device__ __forceinline__ void tmem_wait_ld()  { asm volatile("tcgen05.wait::ld.sync.aligned;" ::: "memory"); }
__device__ __forceinline__ void tc_fence_after(){ asm volatile("tcgen05.fence::after_thread_sync;" ::: "memory"); }

static constexpr uint64_t DESC_BASE_SW128 =
    (uint64_t(2) << 61) | (uint64_t(1) << 46) | (uint64_t(64) << 32) | (uint64_t(1) << 16);
__device__ __forceinline__ uint64_t mk_desc(uint32_t addr) {
    return DESC_BASE_SW128 | ((uint64_t)(addr >> 4) & 0x3FFFull);
}
// idesc: kind::f16, dtype=F32, atype=btype=BF16, M=128, N=128
static constexpr uint32_t IDESC =
    (1u << 4) | (1u << 7) | (1u << 10) | ((128u / 8) << 17) | ((128u / 16) << 24);
#endif  // HAS_TCGEN05

// ---------------------------------------------------------------------------
// bf16 tensor-core GEMM: C[M,N] = A[M,K](bf16 K-major) @ Bw[N,K](bf16 K-major)^T
// CTA tile 256x256, BK=64, 256 threads. (R12 committed design — cp.async only.)
//  - sm_103a pass: WARP-SPECIALIZED tcgen05 pipeline:
//      warps 0-3 producers (cp.async + cp.async.mbarrier.arrive.noinc -> full[b]),
//      warp 4 elect: full-wait -> 16 MMA atoms -> commit empty[b],
//      3-stage 64KB ring, no __syncthreads in the mainloop.
//  - generic pass: mma.sync (HMMA), four 128x128 quadrants (never runs)
// MODE 0: C -> Cf(fp32) and Cbf(bf16), +bias
// MODE 1: C -> Cf, +bias
// MODE 2: C -> Cf, +bias +res
// ---------------------------------------------------------------------------
#define STAGE_BYTES 65536u     // A0(16K) A1(16K) B0(16K) B1(16K)

template<int MODE>
__global__ __launch_bounds__(256)
void mma_gemm(const __nv_bfloat16* __restrict__ A,
              const __nv_bfloat16* __restrict__ Bw,
              const float* __restrict__ bias,
              const float* __restrict__ res,
              float* __restrict__ Cf,
              __nv_bfloat16* __restrict__ Cbf,
              int N, int K)
{
#if HAS_TCGEN05
    // ============ tcgen05 warp-specialized pipeline =========================
    extern __shared__ char dsm[];
    __shared__ uint32_t s_tmem;
    __shared__ __align__(8) uint64_t s_full[3], s_empty[3], s_fin;

    const int tid = threadIdx.x;
    const int wid = tid >> 5;
    const int lid = tid & 31;
    const int n0 = blockIdx.x * 256;
    const int m0 = blockIdx.y * 256;

    const uint32_t tile0 = (smem_u32(dsm) + 1023u) & ~1023u;
    uint32_t fullb[3], emptyb[3];
#pragma unroll
    for (int b = 0; b < 3; b++) {
        fullb[b]  = smem_u32(&s_full[b]);
        emptyb[b] = smem_u32(&s_empty[b]);
    }
    const uint32_t finb = smem_u32(&s_fin);

    if (wid == 0) tmem_alloc(smem_u32(&s_tmem), 512);
    if (tid == 0) {
#pragma unroll
        for (int b = 0; b < 3; b++) { mbar_init(fullb[b], 128); mbar_init(emptyb[b], 1); }
        mbar_init(finb, 1);
    }
    __syncthreads();
    uint32_t tmem;
    asm volatile("ld.shared.b32 %0, [%1];" : "=r"(tmem) : "r"(smem_u32(&s_tmem)));

    const int steps = K >> 6;

    if (tid < 128) {
        // ---------------- producers (warps 0-3) ----------------------------
        // Stage = 512 rows x 128B (A rows 0-255, B rows 256-511).
        // thread t: rt = t>>3 (0..15), off = (t&7)*16; 32 chunks of 16B.
        const int rt  = tid >> 3;
        const int off = (tid & 7) * 16;
        const uint32_t soff = (uint32_t)(off ^ ((rt & 7) << 4));
        const __nv_bfloat16* Abase = A  + (size_t)(m0 + rt) * K + (off >> 1);
        const __nv_bfloat16* Bbase = Bw + (size_t)(n0 + rt) * K + (off >> 1);

        int php[3] = {0, 0, 0};
        for (int c = 0; c < steps; c++) {
            const int b = c % 3;
            if (c >= 3) { mbar_wait(emptyb[b], php[b]); php[b] ^= 1; }
            const uint32_t sbase = tile0 + (uint32_t)b * STAGE_BYTES;
            const __nv_bfloat16* ag = Abase + c * 64;
            const __nv_bfloat16* bg = Bbase + c * 64;
#pragma unroll
            for (int j = 0; j < 16; j++)
                cp16(sbase + (uint32_t)(j * 16 + rt) * 128u + soff,
                     ag + (size_t)j * 16 * K);
#pragma unroll
            for (int j = 0; j < 16; j++)
                cp16(sbase + (uint32_t)(256 + j * 16 + rt) * 128u + soff,
                     bg + (size_t)j * 16 * K);
            cp_mbar_arrive_noinc(fullb[b]);   // arrives when this thread's cps land
        }
    } else if (wid == 4) {
        // ---------------- MMA issuer (warp 4, one thread) -------------------
        if (elect_one()) {
            int phm[3] = {0, 0, 0};
            for (int c = 0; c < steps; c++) {
                const int b = c % 3;
                mbar_wait(fullb[b], phm[b]); phm[b] ^= 1;
                const uint32_t sbase = tile0 + (uint32_t)b * STAGE_BYTES;
                const uint64_t ad0 = mk_desc(sbase);
                const uint64_t ad1 = mk_desc(sbase + 16384u);
                const uint64_t bd0 = mk_desc(sbase + 32768u);
                const uint64_t bd1 = mk_desc(sbase + 49152u);
#pragma unroll
                for (int ss = 0; ss < 4; ss++) {
                    const uint32_t en = (c > 0 || ss > 0) ? 1u : 0u;
                    mma_f16_ss(tmem,       ad0 + ss * 2, bd0 + ss * 2, IDESC, en);
                    mma_f16_ss(tmem + 128, ad1 + ss * 2, bd0 + ss * 2, IDESC, en);
                    mma_f16_ss(tmem + 256, ad0 + ss * 2, bd1 + ss * 2, IDESC, en);
                    mma_f16_ss(tmem + 384, ad1 + ss * 2, bd1 + ss * 2, IDESC, en);
                }
                mma_commit(emptyb[b]);    // buffer reusable when these MMAs finish
            }
            mma_commit(finb);             // all MMAs done
        }
    }
    // warps 5-7 fall through to the epilogue barrier

    __syncthreads();
    mbar_wait(finb, 0);
    tc_fence_after();

    // epilogue: warps 0-3 -> m-half 0 (rows m0+wid*32+lid), warps 4-7 -> m-half 1.
    // atom(mh,nh) at tmem + mh*128 + nh*256; 8 column chunks of 32.
    const int row = m0 + wid * 32 + lid;
    const uint32_t dm = tmem + (uint32_t)((wid >> 2) * 128);
#pragma unroll
    for (int nb = 0; nb < 8; nb++) {
        uint32_t r[32];
        ldtm_x32(r, dm + (uint32_t)((nb >> 2) * 256 + (nb & 3) * 32));
        tmem_wait_ld();
#pragma unroll
        for (int j = 0; j < 32; j += 4) {
            const int n = n0 + nb * 32 + j;
            float4 bv = *reinterpret_cast<const float4*>(bias + n);
            float4 v;
            v.x = __uint_as_float(r[j + 0]) + bv.x;
            v.y = __uint_as_float(r[j + 1]) + bv.y;
            v.z = __uint_as_float(r[j + 2]) + bv.z;
            v.w = __uint_as_float(r[j + 3]) + bv.w;
            if (MODE == 2) {
                float4 rv = *reinterpret_cast<const float4*>(res + (size_t)row * N + n);
                v.x += rv.x; v.y += rv.y; v.z += rv.z; v.w += rv.w;
            }
            *reinterpret_cast<float4*>(Cf + (size_t)row * N + n) = v;
            if (MODE == 0) {
                __nv_bfloat162* cb = reinterpret_cast<__nv_bfloat162*>(Cbf + (size_t)row * N + n);
                cb[0] = __nv_bfloat162(__float2bfloat16(v.x), __float2bfloat16(v.y));
                cb[1] = __nv_bfloat162(__float2bfloat16(v.z), __float2bfloat16(v.w));
            }
        }
    }

    __syncthreads();
    if (wid == 0) tmem_dealloc(tmem, 512);

#else
    // ============ mma.sync fallback: four 128x128 quadrants (never runs) ====
    extern __shared__ char dsm[];
    const uint32_t tile0 = (smem_u32(dsm) + 1023u) & ~1023u;

    const int tid  = threadIdx.x;
    const int lane = tid & 31;
    const int wid  = tid >> 5;
    const int wm   = wid & 3;
    const int wn   = wid >> 2;

    const int ldr = tid >> 1;
    const int ldc = (tid & 1) * 4;

    const int grp = lane >> 3;
    const int l7  = lane & 7;
    const uint32_t a_row = (uint32_t)((grp & 1) * 8 + l7);
    const uint32_t a_kb  = (uint32_t)((grp >> 1) * 16);
    const uint32_t b_row = (uint32_t)((grp >> 1) * 8 + l7);
    const uint32_t b_kb  = (uint32_t)((grp & 1) * 16);

    const int steps = K >> 6;

    for (int hm = 0; hm < 2; hm++)
    for (int hn = 0; hn < 2; hn++) {
        const int m0 = blockIdx.y * 256 + hm * 128;
        const int n0 = blockIdx.x * 256 + hn * 128;

        float acc[2][8][4];
#pragma unroll
        for (int i = 0; i < 2; i++)
#pragma unroll
            for (int j = 0; j < 8; j++)
#pragma unroll
                for (int v = 0; v < 4; v++) acc[i][j][v] = 0.0f;

        auto load_stage = [&](int c) {
            const uint32_t sb = tile0 + (uint32_t)(c & 1) * 32768u;
            const __nv_bfloat16* ag = A  + (size_t)(m0 + ldr) * K + c * 64;
            const __nv_bfloat16* bg = Bw + (size_t)(n0 + ldr) * K + c * 64;
#pragma unroll
            for (int g = 0; g < 4; g++) {
                const uint32_t co = (uint32_t)(ldc + g) * 16u;
                cp16(sb + swz((uint32_t)ldr * 128u + co),            ag + (ldc + g) * 8);
                cp16(sb + 16384u + swz((uint32_t)ldr * 128u + co),   bg + (ldc + g) * 8);
            }
            cp_commit();
        };

        load_stage(0);
        if (steps > 1) load_stage(1);

        for (int s = 0; s < steps; s++) {
            if (s + 2 <= steps) cp_wait1(); else cp_wait0();
            __syncthreads();

            const uint32_t sA = tile0 + (uint32_t)(s & 1) * 32768u;
            const uint32_t sB = sA + 16384u;

#pragma unroll
            for (int ks = 0; ks < 4; ks++) {
                const uint32_t kbase = (uint32_t)ks * 32u;
                uint32_t af[2][4];
#pragma unroll
                for (int mt = 0; mt < 2; mt++) {
                    const uint32_t r = (uint32_t)(wm * 32 + mt * 16) + a_row;
                    ldm_x4(af[mt][0], af[mt][1], af[mt][2], af[mt][3],
                           sA + swz(r * 128u + kbase + a_kb));
                }
                uint32_t bf_[8][2];
#pragma unroll
                for (int nt2 = 0; nt2 < 4; nt2++) {
                    const uint32_t r = (uint32_t)(wn * 64 + nt2 * 16) + b_row;
                    uint32_t r0, r1, r2, r3;
                    ldm_x4(r0, r1, r2, r3, sB + swz(r * 128u + kbase + b_kb));
                    bf_[nt2 * 2 + 0][0] = r0; bf_[nt2 * 2 + 0][1] = r1;
                    bf_[nt2 * 2 + 1][0] = r2; bf_[nt2 * 2 + 1][1] = r3;
                }
#pragma unroll
                for (int mt = 0; mt < 2; mt++)
#pragma unroll
                    for (int nt = 0; nt < 8; nt++)
                        mma_bf16(acc[mt][nt], af[mt], bf_[nt]);
            }

            __syncthreads();
            if (s + 2 < steps) load_stage(s + 2);
        }

#pragma unroll
        for (int mt = 0; mt < 2; mt++) {
            const int rbase = m0 + wm * 32 + mt * 16 + (lane >> 2);
#pragma unroll
            for (int nt = 0; nt < 8; nt++) {
                const int col = n0 + wn * 64 + nt * 8 + 2 * (lane & 3);
                const float2 bv = *reinterpret_cast<const float2*>(bias + col);
#pragma unroll
                for (int h = 0; h < 2; h++) {
                    const int row = rbase + h * 8;
                    float2 v;
                    v.x = acc[mt][nt][h * 2 + 0] + bv.x;
                    v.y = acc[mt][nt][h * 2 + 1] + bv.y;
                    if (MODE == 2) {
                        float2 rv = *reinterpret_cast<const float2*>(res + (size_t)row * N + col);
                        v.x += rv.x; v.y += rv.y;
                    }
                    *reinterpret_cast<float2*>(Cf + (size_t)row * N + col) = v;
                    if (MODE == 0) {
                        *reinterpret_cast<__nv_bfloat162*>(Cbf + (size_t)row * N + col) =
                            __nv_bfloat162(__float2bfloat16(v.x), __float2bfloat16(v.y));
                    }
                }
            }
        }
        __syncthreads();
    }
#endif
}

// ---------------------------------------------------------------------------
// castx: fp32 x -> bf16 xbf (vectorized)
// ---------------------------------------------------------------------------
__global__ __launch_bounds__(256)
void castx_kernel(const float* __restrict__ in, __nv_bfloat16* __restrict__ out)
{
    const size_t i = (size_t)blockIdx.x * 256 + threadIdx.x;   // float4 index
    float4 v = reinterpret_cast<const float4*>(in)[i];
    __nv_bfloat162* o = reinterpret_cast<__nv_bfloat162*>(out) + i * 2;
    o[0] = __nv_bfloat162(__float2bfloat16(v.x), __float2bfloat16(v.y));
    o[1] = __nv_bfloat162(__float2bfloat16(v.z), __float2bfloat16(v.w));
}

// ---------------------------------------------------------------------------
// weightprep: all weight transposes/casts + bias concat in ONE kernel.
//  blocks [0,4096):    Wi [4096,1024] -> wiT [1024,4096]
//  blocks [4096,4608): Wb [1024,512]  -> w23T rows [0,512)
//  blocks [4608,5120): Wf [1024,512]  -> w23T rows [512,1024)
//  blocks [5120,5632): Wo [128,4096]  -> woT [4096,128]
//  block  5632:        bias23 = [bb|bf]
// ---------------------------------------------------------------------------
__global__ __launch_bounds__(256)
void weightprep_kernel(const float* __restrict__ Wi, const float* __restrict__ Wb,
                       const float* __restrict__ Wf, const float* __restrict__ Wo,
                       const float* __restrict__ bb, const float* __restrict__ bf)
{
    __shared__ float t[32][33];
    const int id = blockIdx.x;

    const float* in; __nv_bfloat16* out; int K, N, n0, k0;
    if (id < 4096)      { in = Wi; out = g_wiT;  K = HDIM;    N = DBOT; n0 = (id & 31) * 32;  k0 = (id >> 5) * 32; }
    else if (id < 4608) { int l = id - 4096; in = Wb; out = g_w23T; K = DBOT; N = 512; n0 = (l & 15) * 32; k0 = (l >> 4) * 32; }
    else if (id < 5120) { int l = id - 4608; in = Wf; out = g_w23T + (size_t)512 * DBOT; K = DBOT; N = 512; n0 = (l & 15) * 32; k0 = (l >> 4) * 32; }
    else if (id < 5632) { int l = id - 5120; in = Wo; out = g_woT;  K = COMBDIM; N = HDIM; n0 = (l & 127) * 32; k0 = (l >> 7) * 32; }
    else {
        for (int i = threadIdx.x; i < 512; i += 256) {
            g_bias23[i]       = bb[i];
            g_bias23[i + 512] = bf[i];
        }
        return;
    }

    const int tx = threadIdx.x & 31, ty = threadIdx.x >> 5;   // 32 x 8
#pragma unroll
    for (int i = 0; i < 32; i += 8)
        t[ty + i][tx] = in[(size_t)(k0 + ty + i) * N + n0 + tx];
    __syncthreads();
#pragma unroll
    for (int i = 0; i < 32; i += 8)
        out[(size_t)(n0 + ty + i) * K + k0 + tx] = __float2bfloat16(t[tx][ty + i]);
}

// ---------------------------------------------------------------------------
// w_logits (fp32, reads fp32 h_bot): warp per token, coalesced Ww rows
// ---------------------------------------------------------------------------
__global__ __launch_bounds__(256)
void wlog_kernel(const float* __restrict__ Ww, const float* __restrict__ bw)
{
    const int warp = threadIdx.x >> 5;
    const int lane = threadIdx.x & 31;
    const int t = blockIdx.x * 8 + warp;
    const float* h = g_hbot + (size_t)t * DBOT;

    float acc[PP];
#pragma unroll
    for (int p = 0; p < PP; p++) acc[p] = 0.0f;
#pragma unroll 4
    for (int k = lane; k < DBOT; k += 32) {
        const float hv = h[k];
        float4 w0 = *reinterpret_cast<const float4*>(Ww + (size_t)k * PP);
        float4 w1 = *reinterpret_cast<const float4*>(Ww + (size_t)k * PP + 4);
        acc[0] = fmaf(hv, w0.x, acc[0]); acc[1] = fmaf(hv, w0.y, acc[1]);
        acc[2] = fmaf(hv, w0.z, acc[2]); acc[3] = fmaf(hv, w0.w, acc[3]);
        acc[4] = fmaf(hv, w1.x, acc[4]); acc[5] = fmaf(hv, w1.y, acc[5]);
        acc[6] = fmaf(hv, w1.z, acc[6]); acc[7] = fmaf(hv, w1.w, acc[7]);
    }
#pragma unroll
    for (int p = 0; p < PP; p++)
#pragma unroll
        for (int o = 16; o > 0; o >>= 1)
            acc[p] += __shfl_xor_sync(0xffffffffu, acc[p], o);
    if (lane < PP)
        g_wlog[(size_t)t * PP + lane] = acc[lane] + bw[lane];
}

// ---------------------------------------------------------------------------
// Pointwise: clip base, temporal transport, softmax over P, aggregate -> bf16
// ---------------------------------------------------------------------------
__global__ __launch_bounds__(128)
void pointwise_kernel()
{
    const int t   = blockIdx.x;
    const int bt  = t & (TLEN - 1);
    const int tid = threadIdx.x;

    __shared__ float w[PP];
    if (tid < PP) w[tid] = g_wlog[(size_t)t * PP + tid];
    __syncthreads();
    if (tid == 0) {
        float mx = w[0];
#pragma unroll
        for (int p = 1; p < PP; p++) mx = fmaxf(mx, w[p]);
        float sum = 0.0f;
#pragma unroll
        for (int p = 0; p < PP; p++) { w[p] = __expf(w[p] - mx); sum += w[p]; }
        const float inv = 1.0f / sum;
#pragma unroll
        for (int p = 0; p < PP; p++) w[p] *= inv;
    }
    __syncthreads();

    float out = 0.0f;
    if (tid < DD) {
        const int d = tid;
        const float* bc = g_bf + (size_t)t * DBOT;
        if (bt == 0) {
#pragma unroll
            for (int p = 0; p < PP; p++) {
                float c = fminf(fmaxf(bc[p * DD + d], -10.0f), 10.0f);
                out += w[p] * c;
            }
        } else {
            const float* bp = g_bf + (size_t)(t - 1) * DBOT;
#pragma unroll
            for (int p = 0; p < PP; p++) {
                float c  = fminf(fmaxf(bc[p * DD + d], -10.0f), 10.0f);
                float pv = fminf(fmaxf(bp[p * DD + d], -10.0f), 10.0f);
                out += w[p] * (0.9f * c + 0.1f * pv);
            }
        }
    } else {
        const int kd = tid - DD;
        const float* f = g_bf + (size_t)t * DBOT + 512;
#pragma unroll
        for (int p = 0; p < PP; p++)
            out += w[p] * f[p * DD + kd];
    }
    g_comb_bf[(size_t)t * COMBDIM + tid] = __float2bfloat16(out);
}

// ---------------------------------------------------------------------------
// Inputs: 0:x 1:Wi 2:bi 3:Wb 4:bb 5:Wf 6:bf 7:Wl 8:bl 9:Ww 10:bw
//         11:Wm 12:bm 13:Ws 14:bs 15:Wu 16:bu 17:Wo 18:bo
// ---------------------------------------------------------------------------
static const int SMEM_DYN = 3 * 65536 + 1024;   // 3-stage ring (64KB/stage) + pad

extern "C" void kernel_launch(void* const* d_in, const int* in_sizes, int n_in,
                              void* d_out, int out_size)
{
    const float* x  = (const float*)d_in[0];
    const float* Wi = (const float*)d_in[1];
    const float* bi = (const float*)d_in[2];
    const float* Wb = (const float*)d_in[3];
    const float* bb = (const float*)d_in[4];
    const float* Wf = (const float*)d_in[5];
    const float* bf = (const float*)d_in[6];
    const float* Ww = (const float*)d_in[9];
    const float* bw = (const float*)d_in[10];
    const float* Wo = (const float*)d_in[17];
    const float* bo = (const float*)d_in[18];
    float* out = (float*)d_out;

    float *hbot, *bfc, *b23;
    __nv_bfloat16 *hbotbf, *combbf, *xbf, *wiT, *w23T, *woT;
    cudaGetSymbolAddress((void**)&hbot,   g_hbot);
    cudaGetSymbolAddress((void**)&hbotbf, g_hbot_bf);
    cudaGetSymbolAddress((void**)&bfc,    g_bf);
    cudaGetSymbolAddress((void**)&combbf, g_comb_bf);
    cudaGetSymbolAddress((void**)&xbf,    g_xbf);
    cudaGetSymbolAddress((void**)&wiT,    g_wiT);
    cudaGetSymbolAddress((void**)&w23T,   g_w23T);
    cudaGetSymbolAddress((void**)&woT,    g_woT);
    cudaGetSymbolAddress((void**)&b23,    g_bias23);

    cudaFuncSetAttribute(mma_gemm<0>, cudaFuncAttributeMaxDynamicSharedMemorySize, SMEM_DYN);
    cudaFuncSetAttribute(mma_gemm<1>, cudaFuncAttributeMaxDynamicSharedMemorySize, SMEM_DYN);
    cudaFuncSetAttribute(mma_gemm<2>, cudaFuncAttributeMaxDynamicSharedMemorySize, SMEM_DYN);

    // 0) weight prep (all transposes/casts + bias concat, one kernel)
    weightprep_kernel<<<5633, 256>>>(Wi, Wb, Wf, Wo, bb, bf);                     // 0

    // 1) castx: x -> bf16
    castx_kernel<<<(MTOK * HDIM / 4) / 256, 256>>>(x, xbf);                       // 1

    // 2) GEMM1: h_bot = x @ Wi + bi  [8192,1024], K=4096 (dual fp32+bf16 out)
    mma_gemm<0><<<dim3(DBOT / 256, MTOK / 256), 256, SMEM_DYN>>>(                 // 2
        xbf, wiT, bi, nullptr, hbot, hbotbf, DBOT, HDIM);

    // 3) GEMM23: base|fiber = h_bot @ [Wb|Wf] + bias  [8192,1024], K=1024
    //    (launch idx 3 -> ncu captures a GEMM)
    mma_gemm<1><<<dim3(DBOT / 256, MTOK / 256), 256, SMEM_DYN>>>(                 // 3
        hbotbf, w23T, b23, nullptr, bfc, nullptr, DBOT, DBOT);

    // 4) w_logits (fp32)
    wlog_kernel<<<MTOK / 8, 256>>>(Ww, bw);                                       // 4

    // 5) pointwise: softmax / transport / aggregate -> combined bf16
    pointwise_kernel<<<MTOK, 128>>>();                                            // 5

    // 6) GEMM4: out = x + combined @ Wo + bo  [8192,4096], K=128
    mma_gemm<2><<<dim3(HDIM / 256, MTOK / 256), 256, SMEM_DYN>>>(                 // 6
        combbf, woT, bo, x, out, nullptr, HDIM, COMBDIM);
}